// round 4
// baseline (speedup 1.0000x reference)
#include <cuda_runtime.h>

// Cheb_conv: out[b,o,m,t] = sum_{k,c,n} T[k,n,m] x[b,c,n,t] Theta[k,c,o]
// b=64, c=o=32, n=m=24, t=512, K=3.
// T0=I, T1=L, T2=2L^2-I  =>
//   out = (Th0-Th2)^T X + Th1^T (X L) + 2 Th2^T (X L^2)   per (b,t) slice X[c,n].
//
// R3: packed fp32 math via fma.rn.f32x2 (SASS FFMA2) to halve the FFMA issue
// floor. Thread covers a t-pair; Stage A accumulates (t,t+1) pairs with L/L^2
// pre-duplicated as (L,L | L2,L2); Stage B pairs adjacent o with M stored as
// (o,o+1) float2 pairs; x-side scalars duplicated via mov.b64 (amortized 16x).

#define NV 24
#define NC 32
#define NO 32
#define NT 512
#define NB 64
#define TT 64          // t per block (lane -> t-pair)
#define CCH 4          // c per chunk
#define NCHUNK (NC / CCH)

typedef unsigned long long ull_t;

__device__ __forceinline__ ull_t ffma2(ull_t a, ull_t b, ull_t c) {
    ull_t d;
    asm("fma.rn.f32x2 %0, %1, %2, %3;" : "=l"(d) : "l"(a), "l"(b), "l"(c));
    return d;
}
__device__ __forceinline__ ull_t pack2(float x, float y) {
    ull_t d;
    asm("mov.b64 %0, {%1, %2};" : "=l"(d) : "f"(x), "f"(y));
    return d;
}
__device__ __forceinline__ float2 unpack2(ull_t v) {
    float2 r;
    asm("mov.b64 {%0, %1}, %2;" : "=f"(r.x), "=f"(r.y) : "l"(v));
    return r;
}

// Precomputed operators (written by prep kernel every launch; deterministic).
__device__ float4 g_LLd[NV * NV];       // [n][m] = (L, L, L2, L2)
__device__ float2 g_M2[96 * (NO / 2)];  // [blk*32+c][oo] = (coef[2oo], coef[2oo+1])
                                        // blk0 = Th0-Th2, blk1 = Th1, blk2 = 2*Th2

__global__ void cheb_prep(const float* __restrict__ adj,
                          const float* __restrict__ Theta) {
    __shared__ float dinv[NV];
    __shared__ float L[NV][NV];
    int tid = threadIdx.x;

    if (tid < NV) {
        float s = 0.f;
        #pragma unroll
        for (int j = 0; j < NV; j++) s += adj[tid * NV + j];
        dinv[tid] = (s > 0.f) ? rsqrtf(s) : 0.f;
    }
    __syncthreads();

    for (int idx = tid; idx < NV * NV; idx += blockDim.x) {
        int i = idx / NV, j = idx % NV;
        L[i][j] = adj[j * NV + i] * dinv[i] * dinv[j];
    }
    __syncthreads();

    for (int idx = tid; idx < NV * NV; idx += blockDim.x) {
        int i = idx / NV, j = idx % NV;
        float s = 0.f;
        #pragma unroll
        for (int q = 0; q < NV; q++) s += L[i][q] * L[q][j];
        g_LLd[idx] = make_float4(L[i][j], L[i][j], s, s);
    }

    for (int idx = tid; idx < 96 * (NO / 2); idx += blockDim.x) {
        int j = idx / (NO / 2), oo = idx % (NO / 2);
        int blk = j >> 5, c = j & 31;
        float a, b;
        if (blk == 0) {
            a = Theta[(0 * NC + c) * NO + 2 * oo]     - Theta[(2 * NC + c) * NO + 2 * oo];
            b = Theta[(0 * NC + c) * NO + 2 * oo + 1] - Theta[(2 * NC + c) * NO + 2 * oo + 1];
        } else if (blk == 1) {
            a = Theta[(1 * NC + c) * NO + 2 * oo];
            b = Theta[(1 * NC + c) * NO + 2 * oo + 1];
        } else {
            a = 2.f * Theta[(2 * NC + c) * NO + 2 * oo];
            b = 2.f * Theta[(2 * NC + c) * NO + 2 * oo + 1];
        }
        g_M2[idx] = make_float2(a, b);
    }
}

// Block: (t-chunk of 64, m-group of 8, b). 256 threads = 8 warps.
// warp -> m, lane -> t-pair. X staged per 4-c chunk (24.6 KB); LL dup (9 KB);
// M o-paired (12 KB). Static smem 46 KB -> 2 blocks/SM.
__global__ void __launch_bounds__(256, 2)
cheb_main(const float* __restrict__ x, float* __restrict__ out) {
    __shared__ float  Xs[CCH * NV * TT];   // [4 c][24 n][64 t]
    __shared__ float4 LLs[NV * NV];        // [n][m] dup pairs
    __shared__ float2 Ms[96 * (NO / 2)];   // o-paired weights

    int tid  = threadIdx.x;
    int lane = tid & 31;
    int warp = tid >> 5;
    int b    = blockIdx.z;
    int t0   = blockIdx.x * TT;
    int m    = blockIdx.y * 8 + warp;

    // Stage LL + M once (first chunk's barrier orders them).
    #pragma unroll
    for (int i = tid; i < NV * NV; i += 256) LLs[i] = g_LLd[i];
    #pragma unroll
    for (int i = tid; i < 96 * (NO / 2) / 2; i += 256)
        ((float4*)Ms)[i] = ((const float4*)g_M2)[i];

    ull_t acce[NO / 2], acco[NO / 2];
    #pragma unroll
    for (int oo = 0; oo < NO / 2; oo++) { acce[oo] = 0ull; acco[oo] = 0ull; }

    const float4* xg = (const float4*)(x + ((size_t)b * NC * NV) * NT + t0);

    for (int cc = 0; cc < NCHUNK; cc++) {
        // ---- Fill X chunk: rows (c = cc*4 + r, n), 16 float4 of t each ----
        #pragma unroll
        for (int i = tid; i < CCH * NV * (TT / 4); i += 256) {
            int row = i >> 4, q = i & 15;                 // row = r*24+n
            ((float4*)Xs)[i] = xg[(cc * CCH * NV + row) * (NT / 4) + q];
        }
        __syncthreads();

        // ---- Stage A: (w,v) t-pair accumulation, LL dup from smem ----
        ull_t w2[CCH], v2[CCH];
        #pragma unroll
        for (int c = 0; c < CCH; c++) { w2[c] = 0ull; v2[c] = 0ull; }

        const ull_t* Xs2 = (const ull_t*)Xs;
        #pragma unroll
        for (int n = 0; n < NV; n++) {
            ulonglong2 ll = ((const ulonglong2*)LLs)[n * NV + m];   // (L,L | L2,L2)
            #pragma unroll
            for (int c = 0; c < CCH; c++) {
                ull_t x2 = Xs2[(c * NV + n) * (TT / 2) + lane];
                w2[c] = ffma2(x2, ll.x, w2[c]);
                v2[c] = ffma2(x2, ll.y, v2[c]);
            }
        }
        ull_t xm2[CCH];
        #pragma unroll
        for (int c = 0; c < CCH; c++) xm2[c] = Xs2[(c * NV + m) * (TT / 2) + lane];
        __syncthreads();   // chunk consumed; next fill may overwrite

        // ---- Stage B: o-paired accumulation, x-side dup'd ----
        #pragma unroll
        for (int c = 0; c < CCH; c++) {
            int cg = cc * CCH + c;
            float2 xm_ = unpack2(xm2[c]);
            float2 w_  = unpack2(w2[c]);
            float2 v_  = unpack2(v2[c]);
            ull_t d0e = pack2(xm_.x, xm_.x), d0o = pack2(xm_.y, xm_.y);
            ull_t d1e = pack2(w_.x,  w_.x),  d1o = pack2(w_.y,  w_.y);
            ull_t d2e = pack2(v_.x,  v_.x),  d2o = pack2(v_.y,  v_.y);

            const ulonglong2* M0 = (const ulonglong2*)(Ms + (0 * NC + cg) * (NO / 2));
            const ulonglong2* M1 = (const ulonglong2*)(Ms + (1 * NC + cg) * (NO / 2));
            const ulonglong2* M2p = (const ulonglong2*)(Ms + (2 * NC + cg) * (NO / 2));
            #pragma unroll
            for (int p = 0; p < NO / 4; p++) {            // 2 oo per iter (LDS.128)
                ulonglong2 a  = M0[p];
                ulonglong2 bq = M1[p];
                ulonglong2 cq = M2p[p];
                acce[2 * p]     = ffma2(cq.x, d2e, ffma2(bq.x, d1e, ffma2(a.x, d0e, acce[2 * p])));
                acco[2 * p]     = ffma2(cq.x, d2o, ffma2(bq.x, d1o, ffma2(a.x, d0o, acco[2 * p])));
                acce[2 * p + 1] = ffma2(cq.y, d2e, ffma2(bq.y, d1e, ffma2(a.y, d0e, acce[2 * p + 1])));
                acco[2 * p + 1] = ffma2(cq.y, d2o, ffma2(bq.y, d1o, ffma2(a.y, d0o, acco[2 * p + 1])));
            }
        }
    }

    // ---- Epilogue: transpose (o-pair, t-pair) -> two float2 stores per oo ----
    size_t obase = ((size_t)b * NO * NV) * NT + (size_t)m * NT + t0 + 2 * lane;
    #pragma unroll
    for (int oo = 0; oo < NO / 2; oo++) {
        float2 e = unpack2(acce[oo]);      // (o=2oo, o=2oo+1) at t even
        float2 o_ = unpack2(acco[oo]);     // same at t odd
        *(float2*)&out[obase + (size_t)(2 * oo)     * NV * NT] = make_float2(e.x, o_.x);
        *(float2*)&out[obase + (size_t)(2 * oo + 1) * NV * NT] = make_float2(e.y, o_.y);
    }
}

extern "C" void kernel_launch(void* const* d_in, const int* in_sizes, int n_in,
                              void* d_out, int out_size) {
    const float* x     = (const float*)d_in[0];   // (64,32,24,512)
    const float* adj   = (const float*)d_in[1];   // (24,24)
    const float* Theta = (const float*)d_in[2];   // (3,32,32)
    float* out = (float*)d_out;                   // (64,32,24,512)

    cheb_prep<<<1, 128>>>(adj, Theta);

    dim3 grid(NT / TT, 3, NB);   // 8 t-chunks, 3 m-groups, 64 b = 1536 blocks
    cheb_main<<<grid, 256>>>(x, out);
}

// round 6
// speedup vs baseline: 1.2037x; 1.2037x over previous
#include <cuda_runtime.h>
#include <cuda_fp16.h>
#include <cstdint>

// Cheb_conv as one batched fp16 GEMM on mma.sync (HMMA):
//   out[b,om,t] = sum_cn W[om,cn] * X[b,cn,t]
//   om=o*24+m (768), cn=c*24+n (768), t=512, b=64.
//   W[om,cn] = M0[c,o](n==m) + M1[c,o]L[n,m] + M2[c,o]L2[n,m]
//   M0=Th0-Th2, M1=Th1, M2=2*Th2   (T0=I, T1=L, T2=2L^2-I)
// tcgen05 is unreachable (harness PTX targets compute_103, not 103a), so use
// mma.sync.m16n8k16 f16->f32 which compiles for compute_103.

#define NVERT 24
#define NCH 32
#define NT 512
#define NB 64
#define CN 768
#define OM 768
#define KCH 64          // K chunk (halves)
#define NKCH (CN / KCH) // 12

__device__ float g_L[NVERT * NVERT];
__device__ float g_L2[NVERT * NVERT];
__device__ float g_M[3][NCH][NCH];
__device__ __align__(16) __half g_W[OM * CN];                  // plain row-major [om][cn]
__device__ __align__(16) __half g_Xt[(size_t)NB * NT * CN];    // [b][t][cn] fp16

__device__ __forceinline__ uint32_t smem_u32(const void* p) {
    uint32_t a;
    asm("{ .reg .u64 t; cvta.to.shared.u64 t, %1; cvt.u32.u64 %0, t; }" : "=r"(a) : "l"(p));
    return a;
}
#define CP_ASYNC16(dst, src) \
    asm volatile("cp.async.cg.shared.global [%0], [%1], 16;" :: "r"(dst), "l"(src) : "memory")
#define CP_COMMIT() asm volatile("cp.async.commit_group;" ::: "memory")
#define CP_WAIT1()  asm volatile("cp.async.wait_group 1;" ::: "memory")
#define CP_WAIT0()  asm volatile("cp.async.wait_group 0;" ::: "memory")
#define LDSM_X4(r0, r1, r2, r3, a) \
    asm volatile("ldmatrix.sync.aligned.m8n8.x4.shared.b16 {%0,%1,%2,%3}, [%4];" \
                 : "=r"(r0), "=r"(r1), "=r"(r2), "=r"(r3) : "r"(a))
#define MMA16816(c, a, b0, b1) \
    asm volatile("mma.sync.aligned.m16n8k16.row.col.f32.f16.f16.f32 " \
                 "{%0,%1,%2,%3}, {%4,%5,%6,%7}, {%8,%9}, {%0,%1,%2,%3};" \
                 : "+f"((c)[0]), "+f"((c)[1]), "+f"((c)[2]), "+f"((c)[3]) \
                 : "r"((a)[0]), "r"((a)[1]), "r"((a)[2]), "r"((a)[3]), "r"(b0), "r"(b1))

// ---------------- prep1: L, L2, M ----------------
__global__ void cheb_prep1(const float* __restrict__ adj, const float* __restrict__ Theta) {
    __shared__ float dinv[NVERT];
    __shared__ float L[NVERT][NVERT];
    int tid = threadIdx.x;
    if (tid < NVERT) {
        float s = 0.f;
        #pragma unroll
        for (int j = 0; j < NVERT; j++) s += adj[tid * NVERT + j];
        dinv[tid] = (s > 0.f) ? rsqrtf(s) : 0.f;
    }
    __syncthreads();
    for (int idx = tid; idx < NVERT * NVERT; idx += blockDim.x) {
        int i = idx / NVERT, j = idx % NVERT;
        float v = adj[j * NVERT + i] * dinv[i] * dinv[j];
        L[i][j] = v; g_L[idx] = v;
    }
    __syncthreads();
    for (int idx = tid; idx < NVERT * NVERT; idx += blockDim.x) {
        int i = idx / NVERT, j = idx % NVERT;
        float s = 0.f;
        #pragma unroll
        for (int q = 0; q < NVERT; q++) s += L[i][q] * L[q][j];
        g_L2[idx] = s;
    }
    for (int idx = tid; idx < 3 * NCH * NCH; idx += blockDim.x) {
        int blk = idx / (NCH * NCH), r = idx % (NCH * NCH);
        int c = r / NCH, o = r % NCH;
        float v;
        if (blk == 0)      v = Theta[(0 * NCH + c) * NCH + o] - Theta[(2 * NCH + c) * NCH + o];
        else if (blk == 1) v = Theta[(1 * NCH + c) * NCH + o];
        else               v = 2.f * Theta[(2 * NCH + c) * NCH + o];
        g_M[blk][c][o] = v;
    }
}

// ---------------- prepW: W[om][cn] fp16, plain row-major ----------------
__global__ void cheb_prepW() {
    int idx = blockIdx.x * 256 + threadIdx.x;   // 0 .. 768*768-1
    int om = idx / CN, cn = idx % CN;
    int o = om / NVERT, m = om % NVERT;
    int c = cn / NVERT, n = cn % NVERT;
    float wv = g_M[1][c][o] * g_L[n * NVERT + m] + g_M[2][c][o] * g_L2[n * NVERT + m];
    if (n == m) wv += g_M[0][c][o];
    g_W[idx] = __float2half_rn(wv);
}

// ---------------- xconv: x[b][cn][t] f32 -> g_Xt[b][t][cn] f16 ----------------
__global__ void __launch_bounds__(256) cheb_xconv(const float* __restrict__ x) {
    __shared__ float s[32][33];
    int tid = threadIdx.x, tl = tid & 31, gl = tid >> 5;
    int t0 = blockIdx.x * 32, cn0 = blockIdx.y * 32, b = blockIdx.z;
    const float* src = x + ((size_t)b * CN + cn0) * NT + t0;
    #pragma unroll
    for (int p = 0; p < 4; p++) s[gl + 8 * p][tl] = src[(size_t)(gl + 8 * p) * NT + tl];
    __syncthreads();
    int cp = tid & 15, r0 = tid >> 4;
    #pragma unroll
    for (int q = 0; q < 2; q++) {
        int tr = r0 + 16 * q;
        __half2 h = __floats2half2_rn(s[2 * cp][tr], s[2 * cp + 1][tr]);
        *(__half2*)(g_Xt + ((size_t)b * NT + t0 + tr) * CN + cn0 + 2 * cp) = h;
    }
}

// ---------------- GEMM: CTA 128(om) x 256(t), warp 64x64, K=768 ----------------
// smem (dynamic 96KB): A bufs [2][128 rows x 128B], B bufs [2][256 rows x 128B],
// 16B chunks XOR-swizzled by (row&7) for conflict-free ldmatrix.
#define SM_A(buf) ((buf) * 16384)
#define SM_B(buf) (32768 + (buf) * 32768)
#define SMEM_TOTAL 98304

__device__ __forceinline__ void prefetch_tiles(uint32_t sb, int buf, int kc, int tid,
                                               const __half* Ag, const __half* Bg) {
    const __half* as = Ag + kc * KCH;
    #pragma unroll
    for (int i = 0; i < 4; i++) {
        int idx = tid + 256 * i, row = idx >> 3, ch = idx & 7;
        uint32_t d = sb + SM_A(buf) + row * 128 + ((ch ^ (row & 7)) << 4);
        CP_ASYNC16(d, as + (size_t)row * CN + ch * 8);
    }
    const __half* bs = Bg + kc * KCH;
    #pragma unroll
    for (int i = 0; i < 8; i++) {
        int idx = tid + 256 * i, row = idx >> 3, ch = idx & 7;
        uint32_t d = sb + SM_B(buf) + row * 128 + ((ch ^ (row & 7)) << 4);
        CP_ASYNC16(d, bs + (size_t)row * CN + ch * 8);
    }
    CP_COMMIT();
}

__global__ void __launch_bounds__(256, 1) cheb_gemm(float* __restrict__ out) {
    extern __shared__ __align__(16) unsigned char sm[];
    uint32_t sb = smem_u32(sm);
    int tid = threadIdx.x, lane = tid & 31, warp = tid >> 5;
    int wr = warp & 1, wc = warp >> 1;         // warp grid 2(m) x 4(n)
    int tt = blockIdx.x, omt = blockIdx.y, b = blockIdx.z;

    const __half* Ag = g_W + (size_t)(omt * 128) * CN;
    const __half* Bg = g_Xt + ((size_t)b * NT + tt * 256) * CN;

    float acc[4][8][4];
    #pragma unroll
    for (int mi = 0; mi < 4; mi++)
        #pragma unroll
        for (int nj = 0; nj < 8; nj++)
            #pragma unroll
            for (int q = 0; q < 4; q++) acc[mi][nj][q] = 0.f;

    prefetch_tiles(sb, 0, 0, tid, Ag, Bg);
    prefetch_tiles(sb, 1, 1, tid, Ag, Bg);

    // precomputed fragment address components
    int arow = wr * 64 + (lane & 15);                              // + mi*16
    int ak   = lane >> 4;                                          // k16-chunk parity
    int brow = wc * 64 + (lane & 7) + ((lane >> 4) << 3);          // + nj*16
    int bk   = (lane >> 3) & 1;

    for (int c = 0; c < NKCH; c++) {
        if (c < NKCH - 1) CP_WAIT1(); else CP_WAIT0();
        __syncthreads();
        uint32_t Ab = sb + SM_A(c & 1);
        uint32_t Bb = sb + SM_B(c & 1);

        #pragma unroll
        for (int ks = 0; ks < 4; ks++) {
            uint32_t a[4][4];
            #pragma unroll
            for (int mi = 0; mi < 4; mi++) {
                int row = arow + mi * 16;
                int ch = (ks * 2 + ak) ^ (row & 7);
                LDSM_X4(a[mi][0], a[mi][1], a[mi][2], a[mi][3], Ab + row * 128 + (ch << 4));
            }
            uint32_t bf[8][2];
            #pragma unroll
            for (int nj = 0; nj < 4; nj++) {
                int row = brow + nj * 16;
                int ch = (ks * 2 + bk) ^ (row & 7);
                LDSM_X4(bf[2 * nj][0], bf[2 * nj][1], bf[2 * nj + 1][0], bf[2 * nj + 1][1],
                        Bb + row * 128 + (ch << 4));
            }
            #pragma unroll
            for (int mi = 0; mi < 4; mi++)
                #pragma unroll
                for (int nj = 0; nj < 8; nj++)
                    MMA16816(acc[mi][nj], a[mi], bf[nj][0], bf[nj][1]);
        }
        __syncthreads();
        if (c + 2 < NKCH) prefetch_tiles(sb, c & 1, c + 2, tid, Ag, Bg);
    }

    // epilogue: direct stores (32B sectors: 4 lanes x float2 contiguous in t)
    int om0 = omt * 128 + wr * 64 + (lane >> 2);
    int t0g = tt * 256 + wc * 64 + (lane & 3) * 2;
    #pragma unroll
    for (int mi = 0; mi < 4; mi++) {
        #pragma unroll
        for (int nj = 0; nj < 8; nj++) {
            float* p0 = out + ((size_t)b * OM + om0 + mi * 16) * NT + t0g + nj * 8;
            *(float2*)p0 = make_float2(acc[mi][nj][0], acc[mi][nj][1]);
            *(float2*)(p0 + 8 * NT) = make_float2(acc[mi][nj][2], acc[mi][nj][3]);
        }
    }
}

extern "C" void kernel_launch(void* const* d_in, const int* in_sizes, int n_in,
                              void* d_out, int out_size) {
    const float* x     = (const float*)d_in[0];   // (64,32,24,512)
    const float* adj   = (const float*)d_in[1];   // (24,24)
    const float* Theta = (const float*)d_in[2];   // (3,32,32)
    float* out = (float*)d_out;                   // (64,32,24,512)

    cudaFuncSetAttribute(cheb_gemm, cudaFuncAttributeMaxDynamicSharedMemorySize, SMEM_TOTAL);

    cheb_prep1<<<1, 128>>>(adj, Theta);
    cheb_prepW<<<(OM * CN) / 256, 256>>>();
    cheb_xconv<<<dim3(NT / 32, CN / 32, NB), 256>>>(x);
    cheb_gemm<<<dim3(2, 6, NB), 256, SMEM_TOTAL>>>(out);
}

// round 9
// speedup vs baseline: 1.3557x; 1.1262x over previous
#include <cuda_runtime.h>
#include <cuda_fp16.h>
#include <cstdint>

// Cheb_conv as one batched fp16 GEMM on mma.sync (HMMA):
//   out[b,om,t] = sum_cn W[om,cn] * X[b,cn,t]
//   om=o*24+m (768), cn=c*24+n (768), t=512, b=64.
//   W[om,cn] = M0[c,o](n==m) + M1[c,o]L[n,m] + M2[c,o]L2[n,m]
//   M0=Th0-Th2, M1=Th1, M2=2*Th2   (T0=I, T1=L, T2=2L^2-I)
// R7 (resubmit after infra failure): CTA 128x128, warp 32x64, 2 CTAs/SM to
// lift tensor-pipe occupancy from 51%; xconv rewritten with STG.128 stores.

#define NVERT 24
#define NCH 32
#define NT 512
#define NB 64
#define CN 768
#define OM 768
#define KCH 64          // K chunk (halves) = 128B rows
#define NKCH (CN / KCH) // 12

__device__ float g_L[NVERT * NVERT];
__device__ float g_L2[NVERT * NVERT];
__device__ float g_M[3][NCH][NCH];
__device__ __align__(16) __half g_W[OM * CN];                  // row-major [om][cn]
__device__ __align__(16) __half g_Xt[(size_t)NB * NT * CN];    // [b][t][cn]

__device__ __forceinline__ uint32_t smem_u32(const void* p) {
    uint32_t a;
    asm("{ .reg .u64 t; cvta.to.shared.u64 t, %1; cvt.u32.u64 %0, t; }" : "=r"(a) : "l"(p));
    return a;
}
#define CP_ASYNC16(dst, src) \
    asm volatile("cp.async.cg.shared.global [%0], [%1], 16;" :: "r"(dst), "l"(src) : "memory")
#define CP_COMMIT() asm volatile("cp.async.commit_group;" ::: "memory")
#define CP_WAIT1()  asm volatile("cp.async.wait_group 1;" ::: "memory")
#define CP_WAIT0()  asm volatile("cp.async.wait_group 0;" ::: "memory")
#define LDSM_X4(r0, r1, r2, r3, a) \
    asm volatile("ldmatrix.sync.aligned.m8n8.x4.shared.b16 {%0,%1,%2,%3}, [%4];" \
                 : "=r"(r0), "=r"(r1), "=r"(r2), "=r"(r3) : "r"(a))
#define MMA16816(c, a, b0, b1) \
    asm volatile("mma.sync.aligned.m16n8k16.row.col.f32.f16.f16.f32 " \
                 "{%0,%1,%2,%3}, {%4,%5,%6,%7}, {%8,%9}, {%0,%1,%2,%3};" \
                 : "+f"((c)[0]), "+f"((c)[1]), "+f"((c)[2]), "+f"((c)[3]) \
                 : "r"((a)[0]), "r"((a)[1]), "r"((a)[2]), "r"((a)[3]), "r"(b0), "r"(b1))

// ---------------- prep1: L, L2, M ----------------
__global__ void cheb_prep1(const float* __restrict__ adj, const float* __restrict__ Theta) {
    __shared__ float dinv[NVERT];
    __shared__ float L[NVERT][NVERT];
    int tid = threadIdx.x;
    if (tid < NVERT) {
        float s = 0.f;
        #pragma unroll
        for (int j = 0; j < NVERT; j++) s += adj[tid * NVERT + j];
        dinv[tid] = (s > 0.f) ? rsqrtf(s) : 0.f;
    }
    __syncthreads();
    for (int idx = tid; idx < NVERT * NVERT; idx += blockDim.x) {
        int i = idx / NVERT, j = idx % NVERT;
        float v = adj[j * NVERT + i] * dinv[i] * dinv[j];
        L[i][j] = v; g_L[idx] = v;
    }
    __syncthreads();
    for (int idx = tid; idx < NVERT * NVERT; idx += blockDim.x) {
        int i = idx / NVERT, j = idx % NVERT;
        float s = 0.f;
        #pragma unroll
        for (int q = 0; q < NVERT; q++) s += L[i][q] * L[q][j];
        g_L2[idx] = s;
    }
    for (int idx = tid; idx < 3 * NCH * NCH; idx += blockDim.x) {
        int blk = idx / (NCH * NCH), r = idx % (NCH * NCH);
        int c = r / NCH, o = r % NCH;
        float v;
        if (blk == 0)      v = Theta[(0 * NCH + c) * NCH + o] - Theta[(2 * NCH + c) * NCH + o];
        else if (blk == 1) v = Theta[(1 * NCH + c) * NCH + o];
        else               v = 2.f * Theta[(2 * NCH + c) * NCH + o];
        g_M[blk][c][o] = v;
    }
}

// ---------------- prepW: W[om][cn] fp16, plain row-major ----------------
__global__ void cheb_prepW() {
    int idx = blockIdx.x * 256 + threadIdx.x;
    int om = idx / CN, cn = idx % CN;
    int o = om / NVERT, m = om % NVERT;
    int c = cn / NVERT, n = cn % NVERT;
    float wv = g_M[1][c][o] * g_L[n * NVERT + m] + g_M[2][c][o] * g_L2[n * NVERT + m];
    if (n == m) wv += g_M[0][c][o];
    g_W[idx] = __float2half_rn(wv);
}

// ---------------- xconv: x[b][cn][t] f32 -> g_Xt[b][t][cn] f16, STG.128 ----------------
__global__ void __launch_bounds__(256) cheb_xconv(const float* __restrict__ x) {
    __shared__ float s[128][33];
    int tid = threadIdx.x, tl = tid & 31, gl = tid >> 5;
    int t0 = blockIdx.x * 32, cn0 = blockIdx.y * 128, b = blockIdx.z;
    const float* src = x + ((size_t)b * CN + cn0) * NT + t0;
    #pragma unroll
    for (int p = 0; p < 16; p++) {
        int r = gl + 8 * p;                          // cn row 0..127
        s[r][tl] = src[(size_t)r * NT + tl];
    }
    __syncthreads();
    __half* dst = g_Xt + ((size_t)b * NT + t0) * CN + cn0;
    #pragma unroll
    for (int it = 0; it < 2; it++) {
        int i = tid + 256 * it;                      // 0..511
        int t = i >> 4, ch = i & 15;                 // t row, 8-half chunk along cn
        __half2 h[4];
        #pragma unroll
        for (int q = 0; q < 4; q++)
            h[q] = __floats2half2_rn(s[ch * 8 + 2 * q][t], s[ch * 8 + 2 * q + 1][t]);
        *(float4*)(dst + (size_t)t * CN + ch * 8) = *(float4*)h;
    }
}

// ---------------- GEMM: CTA 128(om) x 128(t), warp 32x64, K=768 ----------------
// smem: A bufs [2][128 x 128B], B bufs [2][128 x 128B], XOR-swizzled 16B chunks.
#define SM_A(buf) ((buf) * 16384)
#define SM_B(buf) (32768 + (buf) * 16384)
#define SMEM_TOTAL 65536

__device__ __forceinline__ void prefetch_tiles(uint32_t sb, int buf, int kc, int tid,
                                               const __half* Ag, const __half* Bg) {
    const __half* as = Ag + kc * KCH;
    #pragma unroll
    for (int i = 0; i < 4; i++) {
        int idx = tid + 256 * i, row = idx >> 3, ch = idx & 7;
        uint32_t d = sb + SM_A(buf) + row * 128 + ((ch ^ (row & 7)) << 4);
        CP_ASYNC16(d, as + (size_t)row * CN + ch * 8);
    }
    const __half* bs = Bg + kc * KCH;
    #pragma unroll
    for (int i = 0; i < 4; i++) {
        int idx = tid + 256 * i, row = idx >> 3, ch = idx & 7;
        uint32_t d = sb + SM_B(buf) + row * 128 + ((ch ^ (row & 7)) << 4);
        CP_ASYNC16(d, bs + (size_t)row * CN + ch * 8);
    }
    CP_COMMIT();
}

__global__ void __launch_bounds__(256, 2) cheb_gemm(float* __restrict__ out) {
    extern __shared__ __align__(16) unsigned char sm[];
    uint32_t sb = smem_u32(sm);
    int tid = threadIdx.x, lane = tid & 31, warp = tid >> 5;
    int wr = warp & 3, wc = warp >> 2;               // 4(m) x 2(n) warps
    int tt = blockIdx.x, omt = blockIdx.y, b = blockIdx.z;

    const __half* Ag = g_W + (size_t)(omt * 128) * CN;
    const __half* Bg = g_Xt + ((size_t)b * NT + tt * 128) * CN;

    float acc[2][8][4];
    #pragma unroll
    for (int mi = 0; mi < 2; mi++)
        #pragma unroll
        for (int nj = 0; nj < 8; nj++)
            #pragma unroll
            for (int q = 0; q < 4; q++) acc[mi][nj][q] = 0.f;

    prefetch_tiles(sb, 0, 0, tid, Ag, Bg);
    prefetch_tiles(sb, 1, 1, tid, Ag, Bg);

    int arow = wr * 32 + (lane & 15);                // + mi*16
    int ak   = lane >> 4;
    int brow = wc * 64 + (lane & 7) + ((lane >> 4) << 3);   // + nj*16
    int bk   = (lane >> 3) & 1;

    for (int c = 0; c < NKCH; c++) {
        if (c < NKCH - 1) CP_WAIT1(); else CP_WAIT0();
        __syncthreads();
        uint32_t Ab = sb + SM_A(c & 1);
        uint32_t Bb = sb + SM_B(c & 1);

        #pragma unroll
        for (int ks = 0; ks < 4; ks++) {
            uint32_t a[2][4];
            #pragma unroll
            for (int mi = 0; mi < 2; mi++) {
                int row = arow + mi * 16;
                int ch = (ks * 2 + ak) ^ (row & 7);
                LDSM_X4(a[mi][0], a[mi][1], a[mi][2], a[mi][3], Ab + row * 128 + (ch << 4));
            }
            uint32_t bf[8][2];
            #pragma unroll
            for (int nj = 0; nj < 4; nj++) {
                int row = brow + nj * 16;
                int ch = (ks * 2 + bk) ^ (row & 7);
                LDSM_X4(bf[2 * nj][0], bf[2 * nj][1], bf[2 * nj + 1][0], bf[2 * nj + 1][1],
                        Bb + row * 128 + (ch << 4));
            }
            #pragma unroll
            for (int mi = 0; mi < 2; mi++)
                #pragma unroll
                for (int nj = 0; nj < 8; nj++)
                    MMA16816(acc[mi][nj], a[mi], bf[nj][0], bf[nj][1]);
        }
        __syncthreads();
        if (c + 2 < NKCH) prefetch_tiles(sb, c & 1, c + 2, tid, Ag, Bg);
    }

    // epilogue: direct float2 stores
    int om0 = omt * 128 + wr * 32 + (lane >> 2);
    int t0g = tt * 128 + wc * 64 + (lane & 3) * 2;
    #pragma unroll
    for (int mi = 0; mi < 2; mi++) {
        #pragma unroll
        for (int nj = 0; nj < 8; nj++) {
            float* p0 = out + ((size_t)b * OM + om0 + mi * 16) * NT + t0g + nj * 8;
            *(float2*)p0 = make_float2(acc[mi][nj][0], acc[mi][nj][1]);
            *(float2*)(p0 + 8 * NT) = make_float2(acc[mi][nj][2], acc[mi][nj][3]);
        }
    }
}

extern "C" void kernel_launch(void* const* d_in, const int* in_sizes, int n_in,
                              void* d_out, int out_size) {
    const float* x     = (const float*)d_in[0];   // (64,32,24,512)
    const float* adj   = (const float*)d_in[1];   // (24,24)
    const float* Theta = (const float*)d_in[2];   // (3,32,32)
    float* out = (float*)d_out;                   // (64,32,24,512)

    cudaFuncSetAttribute(cheb_gemm, cudaFuncAttributeMaxDynamicSharedMemorySize, SMEM_TOTAL);

    cheb_prep1<<<1, 128>>>(adj, Theta);
    cheb_prepW<<<(OM * CN) / 256, 256>>>();
    cheb_xconv<<<dim3(NT / 32, CN / 128, NB), 256>>>(x);
    cheb_gemm<<<dim3(NT / 128, OM / 128, NB), 256, SMEM_TOTAL>>>(out);
}

// round 10
// speedup vs baseline: 1.4130x; 1.0422x over previous
#include <cuda_runtime.h>
#include <cuda_fp16.h>
#include <cstdint>

// Cheb_conv as one batched fp16 GEMM on mma.sync (HMMA):
//   out[b,om,t] = sum_cn W[om,cn] * X[b,cn,t]
//   om=o*24+m (768), cn=c*24+n (768), t=512, b=64.
//   W[om,cn] = M0[c,o](n==m) + M1[c,o]L[n,m] + M2[c,o]L2[n,m]
//   M0=Th0-Th2, M1=Th1, M2=2*Th2   (T0=I, T1=L, T2=2L^2-I)
// R10: 3-stage cp.async pipeline with ONE __syncthreads per K-iter (R9 had 2);
// xconv rewritten with LDG.128/STG.128. Fragment/swizzle math unchanged (proven).

#define NVERT 24
#define NCH 32
#define NT 512
#define NB 64
#define CN 768
#define OM 768
#define KCH 64          // K chunk (halves) = 128B rows
#define NKCH (CN / KCH) // 12

__device__ float g_L[NVERT * NVERT];
__device__ float g_L2[NVERT * NVERT];
__device__ float g_M[3][NCH][NCH];
__device__ __align__(16) __half g_W[OM * CN];                  // row-major [om][cn]
__device__ __align__(16) __half g_Xt[(size_t)NB * NT * CN];    // [b][t][cn]

__device__ __forceinline__ uint32_t smem_u32(const void* p) {
    uint32_t a;
    asm("{ .reg .u64 t; cvta.to.shared.u64 t, %1; cvt.u32.u64 %0, t; }" : "=r"(a) : "l"(p));
    return a;
}
#define CP_ASYNC16(dst, src) \
    asm volatile("cp.async.cg.shared.global [%0], [%1], 16;" :: "r"(dst), "l"(src) : "memory")
#define CP_COMMIT() asm volatile("cp.async.commit_group;" ::: "memory")
#define CP_WAIT1()  asm volatile("cp.async.wait_group 1;" ::: "memory")
#define CP_WAIT0()  asm volatile("cp.async.wait_group 0;" ::: "memory")
#define LDSM_X4(r0, r1, r2, r3, a) \
    asm volatile("ldmatrix.sync.aligned.m8n8.x4.shared.b16 {%0,%1,%2,%3}, [%4];" \
                 : "=r"(r0), "=r"(r1), "=r"(r2), "=r"(r3) : "r"(a))
#define MMA16816(c, a, b0, b1) \
    asm volatile("mma.sync.aligned.m16n8k16.row.col.f32.f16.f16.f32 " \
                 "{%0,%1,%2,%3}, {%4,%5,%6,%7}, {%8,%9}, {%0,%1,%2,%3};" \
                 : "+f"((c)[0]), "+f"((c)[1]), "+f"((c)[2]), "+f"((c)[3]) \
                 : "r"((a)[0]), "r"((a)[1]), "r"((a)[2]), "r"((a)[3]), "r"(b0), "r"(b1))

// ---------------- prep1: L, L2, M ----------------
__global__ void cheb_prep1(const float* __restrict__ adj, const float* __restrict__ Theta) {
    __shared__ float dinv[NVERT];
    __shared__ float L[NVERT][NVERT];
    int tid = threadIdx.x;
    if (tid < NVERT) {
        float s = 0.f;
        #pragma unroll
        for (int j = 0; j < NVERT; j++) s += adj[tid * NVERT + j];
        dinv[tid] = (s > 0.f) ? rsqrtf(s) : 0.f;
    }
    __syncthreads();
    for (int idx = tid; idx < NVERT * NVERT; idx += blockDim.x) {
        int i = idx / NVERT, j = idx % NVERT;
        float v = adj[j * NVERT + i] * dinv[i] * dinv[j];
        L[i][j] = v; g_L[idx] = v;
    }
    __syncthreads();
    for (int idx = tid; idx < NVERT * NVERT; idx += blockDim.x) {
        int i = idx / NVERT, j = idx % NVERT;
        float s = 0.f;
        #pragma unroll
        for (int q = 0; q < NVERT; q++) s += L[i][q] * L[q][j];
        g_L2[idx] = s;
    }
    for (int idx = tid; idx < 3 * NCH * NCH; idx += blockDim.x) {
        int blk = idx / (NCH * NCH), r = idx % (NCH * NCH);
        int c = r / NCH, o = r % NCH;
        float v;
        if (blk == 0)      v = Theta[(0 * NCH + c) * NCH + o] - Theta[(2 * NCH + c) * NCH + o];
        else if (blk == 1) v = Theta[(1 * NCH + c) * NCH + o];
        else               v = 2.f * Theta[(2 * NCH + c) * NCH + o];
        g_M[blk][c][o] = v;
    }
}

// ---------------- prepW: W[om][cn] fp16, plain row-major ----------------
__global__ void cheb_prepW() {
    int idx = blockIdx.x * 256 + threadIdx.x;
    int om = idx / CN, cn = idx % CN;
    int o = om / NVERT, m = om % NVERT;
    int c = cn / NVERT, n = cn % NVERT;
    float wv = g_M[1][c][o] * g_L[n * NVERT + m] + g_M[2][c][o] * g_L2[n * NVERT + m];
    if (n == m) wv += g_M[0][c][o];
    g_W[idx] = __float2half_rn(wv);
}

// ---------------- xconv: x[b][cn][t] f32 -> g_Xt[b][t][cn] f16 ----------------
// Tile 32cn x 128t. LDG.128 along t, padded smem transpose, STG.128 out.
__global__ void __launch_bounds__(256) cheb_xconv(const float* __restrict__ x) {
    __shared__ float s[32][132];
    int tid = threadIdx.x;
    int t0 = blockIdx.x * 128, cn0 = blockIdx.y * 32, b = blockIdx.z;
    const float* src = x + ((size_t)b * CN + cn0) * NT + t0;
    #pragma unroll
    for (int p = 0; p < 4; p++) {
        int i = tid + 256 * p;                       // 0..1023 float4 slots
        int row = i >> 5, q = i & 31;                // cn row, float4 col
        float4 v = *(const float4*)(src + (size_t)row * NT + q * 4);
        *(float4*)&s[row][q * 4] = v;
    }
    __syncthreads();
    __half* dst = g_Xt + ((size_t)b * NT + t0) * CN + cn0;
    #pragma unroll
    for (int p = 0; p < 2; p++) {
        int i = tid + 256 * p;                       // 0..511 output float4 (8 halves)
        int t = i >> 2, h = i & 3;                   // t row, 8-cn chunk
        __half2 hv[4];
        #pragma unroll
        for (int q = 0; q < 4; q++)
            hv[q] = __floats2half2_rn(s[h * 8 + 2 * q][t], s[h * 8 + 2 * q + 1][t]);
        *(float4*)(dst + (size_t)t * CN + h * 8) = *(float4*)hv;
    }
}

// ---------------- GEMM: CTA 128(om) x 128(t), warp 32x64, K=768 ----------------
// smem: 3 stages x (A 16KB + B 16KB) = 96KB, XOR-swizzled 16B chunks.
#define SM_A(s) ((s) * 16384)
#define SM_B(s) (49152 + (s) * 16384)
#define SMEM_TOTAL 98304

__device__ __forceinline__ void prefetch_tiles(uint32_t sb, int buf, int kc, int tid,
                                               const __half* Ag, const __half* Bg) {
    const __half* as = Ag + kc * KCH;
    #pragma unroll
    for (int i = 0; i < 4; i++) {
        int idx = tid + 256 * i, row = idx >> 3, ch = idx & 7;
        uint32_t d = sb + SM_A(buf) + row * 128 + ((ch ^ (row & 7)) << 4);
        CP_ASYNC16(d, as + (size_t)row * CN + ch * 8);
    }
    const __half* bs = Bg + kc * KCH;
    #pragma unroll
    for (int i = 0; i < 4; i++) {
        int idx = tid + 256 * i, row = idx >> 3, ch = idx & 7;
        uint32_t d = sb + SM_B(buf) + row * 128 + ((ch ^ (row & 7)) << 4);
        CP_ASYNC16(d, bs + (size_t)row * CN + ch * 8);
    }
    CP_COMMIT();
}

__global__ void __launch_bounds__(256, 2) cheb_gemm(float* __restrict__ out) {
    extern __shared__ __align__(16) unsigned char sm[];
    uint32_t sb = smem_u32(sm);
    int tid = threadIdx.x, lane = tid & 31, warp = tid >> 5;
    int wr = warp & 3, wc = warp >> 2;               // 4(m) x 2(n) warps
    int tt = blockIdx.x, omt = blockIdx.y, b = blockIdx.z;

    const __half* Ag = g_W + (size_t)(omt * 128) * CN;
    const __half* Bg = g_Xt + ((size_t)b * NT + tt * 128) * CN;

    float acc[2][8][4];
    #pragma unroll
    for (int mi = 0; mi < 2; mi++)
        #pragma unroll
        for (int nj = 0; nj < 8; nj++)
            #pragma unroll
            for (int q = 0; q < 4; q++) acc[mi][nj][q] = 0.f;

    prefetch_tiles(sb, 0, 0, tid, Ag, Bg);
    prefetch_tiles(sb, 1, 1, tid, Ag, Bg);

    int arow = wr * 32 + (lane & 15);                // + mi*16
    int ak   = lane >> 4;
    int brow = wc * 64 + (lane & 7) + ((lane >> 4) << 3);   // + nj*16
    int bk   = (lane >> 3) & 1;

    // 3-stage ring: one __syncthreads per iter. Prefetch for c+2 targets buffer
    // (c+2)%3, which was last read in iter c-1 — all those reads precede this
    // iter's barrier, so no WAR hazard.
    for (int c = 0; c < NKCH; c++) {
        if (c < NKCH - 1) CP_WAIT1(); else CP_WAIT0();
        __syncthreads();
        if (c + 2 < NKCH) prefetch_tiles(sb, (c + 2) % 3, c + 2, tid, Ag, Bg);

        uint32_t Ab = sb + SM_A(c % 3);
        uint32_t Bb = sb + SM_B(c % 3);

        #pragma unroll
        for (int ks = 0; ks < 4; ks++) {
            uint32_t a[2][4];
            #pragma unroll
            for (int mi = 0; mi < 2; mi++) {
                int row = arow + mi * 16;
                int ch = (ks * 2 + ak) ^ (row & 7);
                LDSM_X4(a[mi][0], a[mi][1], a[mi][2], a[mi][3], Ab + row * 128 + (ch << 4));
            }
            uint32_t bf[8][2];
            #pragma unroll
            for (int nj = 0; nj < 4; nj++) {
                int row = brow + nj * 16;
                int ch = (ks * 2 + bk) ^ (row & 7);
                LDSM_X4(bf[2 * nj][0], bf[2 * nj][1], bf[2 * nj + 1][0], bf[2 * nj + 1][1],
                        Bb + row * 128 + (ch << 4));
            }
            #pragma unroll
            for (int mi = 0; mi < 2; mi++)
                #pragma unroll
                for (int nj = 0; nj < 8; nj++)
                    MMA16816(acc[mi][nj], a[mi], bf[nj][0], bf[nj][1]);
        }
    }

    // epilogue: direct float2 stores
    int om0 = omt * 128 + wr * 32 + (lane >> 2);
    int t0g = tt * 128 + wc * 64 + (lane & 3) * 2;
    #pragma unroll
    for (int mi = 0; mi < 2; mi++) {
        #pragma unroll
        for (int nj = 0; nj < 8; nj++) {
            float* p0 = out + ((size_t)b * OM + om0 + mi * 16) * NT + t0g + nj * 8;
            *(float2*)p0 = make_float2(acc[mi][nj][0], acc[mi][nj][1]);
            *(float2*)(p0 + 8 * NT) = make_float2(acc[mi][nj][2], acc[mi][nj][3]);
        }
    }
}

extern "C" void kernel_launch(void* const* d_in, const int* in_sizes, int n_in,
                              void* d_out, int out_size) {
    const float* x     = (const float*)d_in[0];   // (64,32,24,512)
    const float* adj   = (const float*)d_in[1];   // (24,24)
    const float* Theta = (const float*)d_in[2];   // (3,32,32)
    float* out = (float*)d_out;                   // (64,32,24,512)

    cudaFuncSetAttribute(cheb_gemm, cudaFuncAttributeMaxDynamicSharedMemorySize, SMEM_TOTAL);

    cheb_prep1<<<1, 128>>>(adj, Theta);
    cheb_prepW<<<(OM * CN) / 256, 256>>>();
    cheb_xconv<<<dim3(NT / 128, CN / 32, NB), 256>>>(x);
    cheb_gemm<<<dim3(NT / 128, OM / 128, NB), 256, SMEM_TOTAL>>>(out);
}